// round 4
// baseline (speedup 1.0000x reference)
#include <cuda_runtime.h>
#include <cstdint>

// Problem constants
#define BATCH 256
#define SEQ   128
#define D_IN  1024
#define D_HID 2048
#define N_CLS 1024

// Scratch (no cudaMalloc allowed): xproj [B,S,H] + ping-pong h buffers
__device__ float g_xproj[(size_t)BATCH * SEQ * D_HID];   // 268 MB
__device__ float g_hbuf[2][(size_t)BATCH * D_HID];       // 2 x 2 MB

// ---------------------------------------------------------------------------
// Generic NT SGEMM: C[m,n] = sum_k A[m,k] * B[n,k]  (+ Add[m,n]) (+ bias[n])
// A: [M,K] row-major with leading dim lda
// B: [N,K] row-major, ldb == K (weights)
// Add: row stride ldadd (used for the xproj[:,t,:] slice view)
// All dims are multiples of tile sizes for this problem: no bounds checks.
// ---------------------------------------------------------------------------
template <int BM, int BN, int BK, int TM, int TN, bool ADD, bool BIAS>
__global__ __launch_bounds__(256, 2) void sgemm_nt(
    int M, int N, int K,
    const float* __restrict__ A, int lda,
    const float* __restrict__ B,
    const float* __restrict__ Add, int ldadd,
    const float* __restrict__ bias,
    float* __restrict__ C)
{
    constexpr int THREADS = (BM / TM) * (BN / TN);
    constexpr int PAD = 4;  // keeps 16B alignment of rows, perturbs banks

    __shared__ float As[BK][BM + PAD];
    __shared__ float Bs[BK][BN + PAD];

    const int tid = threadIdx.x;
    const int bn = blockIdx.x;  // N tile
    const int bm = blockIdx.y;  // M tile

    const int tx = tid % (BN / TN);
    const int ty = tid / (BN / TN);

    float acc[TM][TN];
#pragma unroll
    for (int i = 0; i < TM; i++)
#pragma unroll
        for (int j = 0; j < TN; j++) acc[i][j] = 0.0f;

    const float* Ab = A + (size_t)bm * BM * lda;
    const float* Bb = B + (size_t)bn * BN * K;

    for (int kt = 0; kt < K; kt += BK) {
        // --- load A tile (BM x BK), float4 along K, transpose into As[k][m]
        constexpr int KV = BK / 4;
#pragma unroll
        for (int idx = tid; idx < BM * KV; idx += THREADS) {
            int r  = idx / KV;
            int c4 = (idx % KV) * 4;
            float4 v = *reinterpret_cast<const float4*>(Ab + (size_t)r * lda + kt + c4);
            As[c4 + 0][r] = v.x;
            As[c4 + 1][r] = v.y;
            As[c4 + 2][r] = v.z;
            As[c4 + 3][r] = v.w;
        }
        // --- load B tile (BN x BK)
#pragma unroll
        for (int idx = tid; idx < BN * KV; idx += THREADS) {
            int r  = idx / KV;
            int c4 = (idx % KV) * 4;
            float4 v = *reinterpret_cast<const float4*>(Bb + (size_t)r * K + kt + c4);
            Bs[c4 + 0][r] = v.x;
            Bs[c4 + 1][r] = v.y;
            Bs[c4 + 2][r] = v.z;
            Bs[c4 + 3][r] = v.w;
        }
        __syncthreads();

#pragma unroll
        for (int k = 0; k < BK; k++) {
            float a[TM], b[TN];
#pragma unroll
            for (int i = 0; i < TM; i += 4)
                *reinterpret_cast<float4*>(&a[i]) =
                    *reinterpret_cast<const float4*>(&As[k][ty * TM + i]);
#pragma unroll
            for (int j = 0; j < TN; j += 4)
                *reinterpret_cast<float4*>(&b[j]) =
                    *reinterpret_cast<const float4*>(&Bs[k][tx * TN + j]);
#pragma unroll
            for (int i = 0; i < TM; i++)
#pragma unroll
                for (int j = 0; j < TN; j++)
                    acc[i][j] = fmaf(a[i], b[j], acc[i][j]);
        }
        __syncthreads();
    }

    // --- epilogue ---
#pragma unroll
    for (int i = 0; i < TM; i++) {
        const int row = bm * BM + ty * TM + i;
#pragma unroll
        for (int j = 0; j < TN; j += 4) {
            const int col = bn * BN + tx * TN + j;
            float4 v = make_float4(acc[i][j], acc[i][j + 1], acc[i][j + 2], acc[i][j + 3]);
            if (ADD) {
                float4 ad = *reinterpret_cast<const float4*>(&Add[(size_t)row * ldadd + col]);
                v.x += ad.x; v.y += ad.y; v.z += ad.z; v.w += ad.w;
            }
            if (BIAS) {
                float4 bb = *reinterpret_cast<const float4*>(&bias[col]);
                v.x += bb.x; v.y += bb.y; v.z += bb.z; v.w += bb.w;
            }
            *reinterpret_cast<float4*>(&C[(size_t)row * N + col]) = v;
        }
    }
}

extern "C" void kernel_launch(void* const* d_in, const int* in_sizes, int n_in,
                              void* d_out, int out_size)
{
    const float* x    = (const float*)d_in[0];  // [B,S,D_IN]
    const float* W_hx = (const float*)d_in[1];  // [H, D_IN]
    const float* W_hh = (const float*)d_in[2];  // [H, H]
    const float* W_ph = (const float*)d_in[3];  // [C, H]
    const float* b_h  = (const float*)d_in[4];  // [H]
    const float* b_p  = (const float*)d_in[5];  // [C]
    float* out = (float*)d_out;                 // [B, C]

    float* xproj = nullptr;
    float* hbuf  = nullptr;
    cudaGetSymbolAddress((void**)&xproj, g_xproj);
    cudaGetSymbolAddress((void**)&hbuf,  g_hbuf);
    float* h0 = hbuf;
    float* h1 = hbuf + (size_t)BATCH * D_HID;
    float* bufs[2] = {h0, h1};

    // 1) xproj[b,s,:] = x[b,s,:] @ W_hx^T + b_h   (M=32768, N=2048, K=1024)
    {
        dim3 grid(D_HID / 128, (BATCH * SEQ) / 128);
        sgemm_nt<128, 128, 16, 8, 8, false, true><<<grid, 256>>>(
            BATCH * SEQ, D_HID, D_IN,
            x, D_IN, W_hx, nullptr, 0, b_h, xproj);
    }

    // 2) recurrence: s_0 = xp_0 (read in place via strided lda);
    //    s_t = xp_t + s_{t-1} @ W_hh^T   for t = 1..127
    const float* hin = xproj;       // xp_0 slice: rows stride SEQ*D_HID
    int ldah = SEQ * D_HID;
    for (int t = 1; t < SEQ; t++) {
        float* hout = bufs[t & 1];
        dim3 grid(D_HID / 64, BATCH / 64);
        sgemm_nt<64, 64, 16, 4, 4, true, false><<<grid, 256>>>(
            BATCH, D_HID, D_HID,
            hin, ldah, W_hh,
            xproj + (size_t)t * D_HID, SEQ * D_HID,
            nullptr, hout);
        hin = hout;
        ldah = D_HID;
    }

    // 3) readout: out = h_T @ W_ph^T + b_p   (M=256, N=1024, K=2048)
    {
        dim3 grid(N_CLS / 64, BATCH / 64);
        sgemm_nt<64, 64, 16, 4, 4, false, true><<<grid, 256>>>(
            BATCH, N_CLS, D_HID,
            hin, D_HID, W_ph, nullptr, 0, b_p, out);
    }
}

// round 10
// speedup vs baseline: 2.3194x; 2.3194x over previous
#include <cuda_runtime.h>
#include <cuda_bf16.h>
#include <cstdint>

#define BATCH 256
#define SEQ   128
#define D_IN  1024
#define D_HID 2048
#define N_CLS 1024

// ---------------- scratch (__device__ globals; no cudaMalloc allowed) -------
__device__ float         g_xproj[(size_t)BATCH * SEQ * D_HID];          // 268 MB
__device__ __nv_bfloat16 g_x_hi [(size_t)BATCH * SEQ * D_IN];
__device__ __nv_bfloat16 g_x_lo [(size_t)BATCH * SEQ * D_IN];
__device__ __nv_bfloat16 g_Whh_hi[(size_t)D_HID * D_HID];
__device__ __nv_bfloat16 g_Whh_lo[(size_t)D_HID * D_HID];
__device__ __nv_bfloat16 g_Whx_hi[(size_t)D_HID * D_IN];
__device__ __nv_bfloat16 g_Whx_lo[(size_t)D_HID * D_IN];
__device__ __nv_bfloat16 g_Wph_hi[(size_t)N_CLS * D_HID];
__device__ __nv_bfloat16 g_Wph_lo[(size_t)N_CLS * D_HID];
__device__ __nv_bfloat16 g_h_hi[2][(size_t)BATCH * D_HID];
__device__ __nv_bfloat16 g_h_lo[2][(size_t)BATCH * D_HID];

// ---------------- portable PTX helpers (compute_103 baseline, no 'a') -------
__device__ __forceinline__ uint32_t smem_to_u32(const void* p) {
    uint32_t a;
    asm("{ .reg .u64 t; cvta.to.shared.u64 t, %1; cvt.u32.u64 %0, t; }" : "=r"(a) : "l"(p));
    return a;
}
#define CP_ASYNC16(dst, src) \
    asm volatile("cp.async.cg.shared.global [%0], [%1], 16;" :: "r"(dst), "l"(src) : "memory")
#define CP_COMMIT() asm volatile("cp.async.commit_group;" ::: "memory")
#define CP_WAIT0()  asm volatile("cp.async.wait_group 0;" ::: "memory")
#define CP_WAIT1()  asm volatile("cp.async.wait_group 1;" ::: "memory")

__device__ __forceinline__ void ldsm_x4(uint32_t* r, uint32_t addr) {
    asm volatile("ldmatrix.sync.aligned.m8n8.x4.shared.b16 {%0,%1,%2,%3}, [%4];"
                 : "=r"(r[0]), "=r"(r[1]), "=r"(r[2]), "=r"(r[3]) : "r"(addr));
}
__device__ __forceinline__ void mma_bf16(float* c, const uint32_t* a, const uint32_t* b) {
    asm volatile("mma.sync.aligned.m16n8k16.row.col.f32.bf16.bf16.f32 "
                 "{%0,%1,%2,%3}, {%4,%5,%6,%7}, {%8,%9}, {%0,%1,%2,%3};"
                 : "+f"(c[0]), "+f"(c[1]), "+f"(c[2]), "+f"(c[3])
                 : "r"(a[0]), "r"(a[1]), "r"(a[2]), "r"(a[3]), "r"(b[0]), "r"(b[1]));
}
__device__ __forceinline__ uint32_t swz(uint32_t off) {   // SW128-style XOR swizzle
    return off ^ ((off >> 3) & 0x70);
}

// ---------------------------------------------------------------------------
// HMMA split-bf16 GEMM: C[m,n] = sum_k A[m,k]*B[n,k] over 3 passes
// (Ahi.Bhi + Ahi.Blo + Alo.Bhi), fp32 accum.
// A:[M,K] row-major, B:[N,K] row-major (== col-major B operand for mma).
// BM=BN=64, BK=64, 128 threads (4 warps 2x2, 32x32 warp tile).
// ---------------------------------------------------------------------------
template <bool ADD, bool BIAS, bool OUT_SPLIT>
__global__ __launch_bounds__(128) void rnn_gemm(
    int M, int N, int K,
    const __nv_bfloat16* __restrict__ Ahi, const __nv_bfloat16* __restrict__ Alo,
    const __nv_bfloat16* __restrict__ Bhi, const __nv_bfloat16* __restrict__ Blo,
    const float* __restrict__ Add, int ldadd,
    const float* __restrict__ bias,
    float* __restrict__ C,
    __nv_bfloat16* __restrict__ Chi, __nv_bfloat16* __restrict__ Clo)
{
    __shared__ __align__(1024) char smem[4 * 8192];  // A[2], B[2] tiles, 8KB each
    const uint32_t sbase = smem_to_u32(smem);

    const int tid  = threadIdx.x;
    const int lane = tid & 31;
    const int wid  = tid >> 5;
    const int warp_m = wid & 1;         // 2 warps along M
    const int warp_n = wid >> 1;        // 2 warps along N
    const int bn = blockIdx.x;
    const int bm = blockIdx.y;

    const int NITP = K >> 6;
    const int NIT  = 3 * NITP;

    auto issueTiles = [&](int it, int buf) {
        const int pass = it / NITP;
        const int kb = (it - pass * NITP) << 6;
        const __nv_bfloat16* Ap = (pass == 2) ? Alo : Ahi;
        const __nv_bfloat16* Bp = (pass == 1) ? Blo : Bhi;
        const char* Ag = (const char*)(Ap + (size_t)(bm * 64) * K + kb);
        const char* Bg = (const char*)(Bp + (size_t)(bn * 64) * K + kb);
        const uint32_t sA = sbase + buf * 8192;
        const uint32_t sB = sbase + 16384 + buf * 8192;
        const size_t rs = (size_t)K * 2;
#pragma unroll
        for (int j = 0; j < 4; j++) {        // 512 16B chunks per tile / 128 thr
            int c = tid + j * 128;
            int r = c >> 3, col = (c & 7) << 4;
            uint32_t off = swz((uint32_t)(r * 128 + col));
            CP_ASYNC16(sA + off, Ag + (size_t)r * rs + col);
            CP_ASYNC16(sB + off, Bg + (size_t)r * rs + col);
        }
    };

    float acc[2][4][4];
#pragma unroll
    for (int i = 0; i < 2; i++)
#pragma unroll
        for (int j = 0; j < 4; j++)
#pragma unroll
            for (int e = 0; e < 4; e++) acc[i][j][e] = 0.0f;

    issueTiles(0, 0);
    CP_COMMIT();

    for (int it = 0; it < NIT; it++) {
        const int buf = it & 1;
        if (it + 1 < NIT) {
            issueTiles(it + 1, buf ^ 1);
            CP_COMMIT();
            CP_WAIT1();                  // oldest group (tiles for `it`) complete
        } else {
            CP_WAIT0();
        }
        __syncthreads();

        const uint32_t sA = sbase + buf * 8192;
        const uint32_t sB = sbase + 16384 + buf * 8192;
#pragma unroll
        for (int s = 0; s < 4; s++) {    // 4 x k16 within BK=64
            const int k0 = s * 16;
            uint32_t a[2][4], b[2][4];
#pragma unroll
            for (int i = 0; i < 2; i++) {
                int row = warp_m * 32 + i * 16 + (lane & 15);
                int kc  = k0 + (lane >> 4) * 8;
                ldsm_x4(a[i], sA + swz((uint32_t)(row * 128 + kc * 2)));
            }
#pragma unroll
            for (int jj = 0; jj < 2; jj++) {
                int n  = warp_n * 32 + jj * 16 + (lane & 7) + ((lane >> 4) & 1) * 8;
                int kc = k0 + ((lane >> 3) & 1) * 8;
                ldsm_x4(b[jj], sB + swz((uint32_t)(n * 128 + kc * 2)));
            }
#pragma unroll
            for (int i = 0; i < 2; i++)
#pragma unroll
                for (int j = 0; j < 4; j++)
                    mma_bf16(acc[i][j], a[i], &b[j >> 1][(j & 1) * 2]);
        }
        __syncthreads();
    }

    // ---- epilogue ----
    const int tg = lane >> 2, tr = lane & 3;
    const int m_base = bm * 64 + warp_m * 32;
    const int n_base = bn * 64 + warp_n * 32;
#pragma unroll
    for (int i = 0; i < 2; i++) {
#pragma unroll
        for (int j = 0; j < 4; j++) {
            const int col  = n_base + j * 8 + tr * 2;
            const int row0 = m_base + i * 16 + tg;
            const int row1 = row0 + 8;
            float2 v0 = make_float2(acc[i][j][0], acc[i][j][1]);
            float2 v1 = make_float2(acc[i][j][2], acc[i][j][3]);
            if (ADD) {
                float2 a0 = *(const float2*)&Add[(size_t)row0 * ldadd + col];
                float2 a1 = *(const float2*)&Add[(size_t)row1 * ldadd + col];
                v0.x += a0.x; v0.y += a0.y; v1.x += a1.x; v1.y += a1.y;
            }
            if (BIAS) {
                float2 bb = *(const float2*)&bias[col];
                v0.x += bb.x; v0.y += bb.y; v1.x += bb.x; v1.y += bb.y;
            }
            if (OUT_SPLIT) {
                __nv_bfloat16 h0 = __float2bfloat16(v0.x), h1 = __float2bfloat16(v0.y);
                __nv_bfloat16 h2 = __float2bfloat16(v1.x), h3 = __float2bfloat16(v1.y);
                __nv_bfloat16 l0 = __float2bfloat16(v0.x - __bfloat162float(h0));
                __nv_bfloat16 l1 = __float2bfloat16(v0.y - __bfloat162float(h1));
                __nv_bfloat16 l2 = __float2bfloat16(v1.x - __bfloat162float(h2));
                __nv_bfloat16 l3 = __float2bfloat16(v1.y - __bfloat162float(h3));
                __nv_bfloat162 hp0{h0, h1}, hp1{h2, h3}, lp0{l0, l1}, lp1{l2, l3};
                *(uint32_t*)&Chi[(size_t)row0 * N + col] = *(uint32_t*)&hp0;
                *(uint32_t*)&Chi[(size_t)row1 * N + col] = *(uint32_t*)&hp1;
                *(uint32_t*)&Clo[(size_t)row0 * N + col] = *(uint32_t*)&lp0;
                *(uint32_t*)&Clo[(size_t)row1 * N + col] = *(uint32_t*)&lp1;
            } else {
                *(float2*)&C[(size_t)row0 * N + col] = v0;
                *(float2*)&C[(size_t)row1 * N + col] = v1;
            }
        }
    }
}

// ---------------- fp32 -> bf16 hi/lo split kernels --------------------------
__global__ void split_kernel(const float* __restrict__ src,
                             __nv_bfloat16* __restrict__ hi, __nv_bfloat16* __restrict__ lo,
                             size_t n4)
{
    size_t i = (size_t)blockIdx.x * blockDim.x + threadIdx.x;
    if (i >= n4) return;
    float4 v = ((const float4*)src)[i];
    __nv_bfloat16 h0 = __float2bfloat16(v.x), h1 = __float2bfloat16(v.y);
    __nv_bfloat16 h2 = __float2bfloat16(v.z), h3 = __float2bfloat16(v.w);
    __nv_bfloat16 l0 = __float2bfloat16(v.x - __bfloat162float(h0));
    __nv_bfloat16 l1 = __float2bfloat16(v.y - __bfloat162float(h1));
    __nv_bfloat16 l2 = __float2bfloat16(v.z - __bfloat162float(h2));
    __nv_bfloat16 l3 = __float2bfloat16(v.w - __bfloat162float(h3));
    __nv_bfloat162 hp0{h0, h1}, hp1{h2, h3}, lp0{l0, l1}, lp1{l2, l3};
    uint2 hw, lw;
    hw.x = *(uint32_t*)&hp0; hw.y = *(uint32_t*)&hp1;
    lw.x = *(uint32_t*)&lp0; lw.y = *(uint32_t*)&lp1;
    ((uint2*)hi)[i] = hw;
    ((uint2*)lo)[i] = lw;
}

__global__ void split_h0_kernel(const float* __restrict__ xproj,
                                __nv_bfloat16* __restrict__ hi, __nv_bfloat16* __restrict__ lo)
{
    size_t i = (size_t)blockIdx.x * blockDim.x + threadIdx.x;
    size_t n4 = (size_t)BATCH * D_HID / 4;
    if (i >= n4) return;
    size_t e = i * 4;
    size_t b = e / D_HID, c = e % D_HID;
    float4 v = *(const float4*)&xproj[b * (size_t)SEQ * D_HID + c];
    __nv_bfloat16 h0 = __float2bfloat16(v.x), h1 = __float2bfloat16(v.y);
    __nv_bfloat16 h2 = __float2bfloat16(v.z), h3 = __float2bfloat16(v.w);
    __nv_bfloat16 l0 = __float2bfloat16(v.x - __bfloat162float(h0));
    __nv_bfloat16 l1 = __float2bfloat16(v.y - __bfloat162float(h1));
    __nv_bfloat16 l2 = __float2bfloat16(v.z - __bfloat162float(h2));
    __nv_bfloat16 l3 = __float2bfloat16(v.w - __bfloat162float(h3));
    __nv_bfloat162 hp0{h0, h1}, hp1{h2, h3}, lp0{l0, l1}, lp1{l2, l3};
    uint2 hw, lw;
    hw.x = *(uint32_t*)&hp0; hw.y = *(uint32_t*)&hp1;
    lw.x = *(uint32_t*)&lp0; lw.y = *(uint32_t*)&lp1;
    ((uint2*)hi)[i] = hw;
    ((uint2*)lo)[i] = lw;
}

// ---------------------------------------------------------------------------
extern "C" void kernel_launch(void* const* d_in, const int* in_sizes, int n_in,
                              void* d_out, int out_size)
{
    const float* x    = (const float*)d_in[0];
    const float* W_hx = (const float*)d_in[1];
    const float* W_hh = (const float*)d_in[2];
    const float* W_ph = (const float*)d_in[3];
    const float* b_h  = (const float*)d_in[4];
    const float* b_p  = (const float*)d_in[5];
    float* out = (float*)d_out;

    float* xproj; __nv_bfloat16 *x_hi, *x_lo, *whh_hi, *whh_lo, *whx_hi, *whx_lo,
                  *wph_hi, *wph_lo, *h_hi, *h_lo;
    cudaGetSymbolAddress((void**)&xproj,  g_xproj);
    cudaGetSymbolAddress((void**)&x_hi,   g_x_hi);
    cudaGetSymbolAddress((void**)&x_lo,   g_x_lo);
    cudaGetSymbolAddress((void**)&whh_hi, g_Whh_hi);
    cudaGetSymbolAddress((void**)&whh_lo, g_Whh_lo);
    cudaGetSymbolAddress((void**)&whx_hi, g_Whx_hi);
    cudaGetSymbolAddress((void**)&whx_lo, g_Whx_lo);
    cudaGetSymbolAddress((void**)&wph_hi, g_Wph_hi);
    cudaGetSymbolAddress((void**)&wph_lo, g_Wph_lo);
    cudaGetSymbolAddress((void**)&h_hi,   g_h_hi);
    cudaGetSymbolAddress((void**)&h_lo,   g_h_lo);

    // 0) splits of inputs/weights
    {
        size_t n4;
        n4 = (size_t)BATCH * SEQ * D_IN / 4;
        split_kernel<<<(unsigned)((n4 + 255) / 256), 256>>>(x, x_hi, x_lo, n4);
        n4 = (size_t)D_HID * D_HID / 4;
        split_kernel<<<(unsigned)((n4 + 255) / 256), 256>>>(W_hh, whh_hi, whh_lo, n4);
        n4 = (size_t)D_HID * D_IN / 4;
        split_kernel<<<(unsigned)((n4 + 255) / 256), 256>>>(W_hx, whx_hi, whx_lo, n4);
        n4 = (size_t)N_CLS * D_HID / 4;
        split_kernel<<<(unsigned)((n4 + 255) / 256), 256>>>(W_ph, wph_hi, wph_lo, n4);
    }

    // 1) xproj = x @ W_hx^T + b_h   (M=32768, N=2048, K=1024) -> fp32
    {
        dim3 grid(D_HID / 64, (BATCH * SEQ) / 64);
        rnn_gemm<false, true, false><<<grid, 128>>>(
            BATCH * SEQ, D_HID, D_IN,
            x_hi, x_lo, whx_hi, whx_lo,
            nullptr, 0, b_h, xproj, nullptr, nullptr);
    }

    // 2) h0 = xp_0 -> bf16 hi/lo
    {
        size_t n4 = (size_t)BATCH * D_HID / 4;
        split_h0_kernel<<<(unsigned)((n4 + 255) / 256), 256>>>(xproj, h_hi, h_lo);
    }

    // 3) recurrence: h_t = xp_t + h_{t-1} @ W_hh^T  (M=256, N=2048, K=2048)
    const size_t HB = (size_t)BATCH * D_HID;
    int cur = 0;
    for (int t = 1; t < SEQ; t++) {
        int nxt = t & 1;
        dim3 grid(D_HID / 64, BATCH / 64);
        rnn_gemm<true, false, true><<<grid, 128>>>(
            BATCH, D_HID, D_HID,
            h_hi + (size_t)cur * HB, h_lo + (size_t)cur * HB,
            whh_hi, whh_lo,
            xproj + (size_t)t * D_HID, SEQ * D_HID,
            nullptr, nullptr,
            h_hi + (size_t)nxt * HB, h_lo + (size_t)nxt * HB);
        cur = nxt;
    }

    // 4) readout: out = h_T @ W_ph^T + b_p  (M=256, N=1024, K=2048) -> fp32
    {
        dim3 grid(N_CLS / 64, BATCH / 64);
        rnn_gemm<false, true, false><<<grid, 128>>>(
            BATCH, N_CLS, D_HID,
            h_hi + (size_t)cur * HB, h_lo + (size_t)cur * HB,
            wph_hi, wph_lo,
            nullptr, 0, b_p, out, nullptr, nullptr);
    }
}

// round 12
// speedup vs baseline: 4.0563x; 1.7489x over previous
#include <cuda_runtime.h>
#include <cuda_bf16.h>
#include <cstdint>

#define BATCH 256
#define SEQ   128
#define D_IN  1024
#define D_HID 2048
#define N_CLS 1024

// ---------------- scratch (__device__ globals; no cudaMalloc allowed) -------
__device__ float         g_xproj[(size_t)BATCH * SEQ * D_HID];          // 268 MB
__device__ __nv_bfloat16 g_x_hi [(size_t)BATCH * SEQ * D_IN];
__device__ __nv_bfloat16 g_x_lo [(size_t)BATCH * SEQ * D_IN];
__device__ __nv_bfloat16 g_Whh_hi[(size_t)D_HID * D_HID];
__device__ __nv_bfloat16 g_Whh_lo[(size_t)D_HID * D_HID];
__device__ __nv_bfloat16 g_Whx_hi[(size_t)D_HID * D_IN];
__device__ __nv_bfloat16 g_Whx_lo[(size_t)D_HID * D_IN];
__device__ __nv_bfloat16 g_Wph_hi[(size_t)N_CLS * D_HID];
__device__ __nv_bfloat16 g_Wph_lo[(size_t)N_CLS * D_HID];
__device__ __nv_bfloat16 g_h_hi[2][(size_t)BATCH * D_HID];
__device__ __nv_bfloat16 g_h_lo[2][(size_t)BATCH * D_HID];

// ---------------- portable PTX helpers (compute_103 baseline, no 'a') -------
__device__ __forceinline__ uint32_t smem_to_u32(const void* p) {
    uint32_t a;
    asm("{ .reg .u64 t; cvta.to.shared.u64 t, %1; cvt.u32.u64 %0, t; }" : "=r"(a) : "l"(p));
    return a;
}
#define CP_ASYNC16(dst, src) \
    asm volatile("cp.async.cg.shared.global [%0], [%1], 16;" :: "r"(dst), "l"(src) : "memory")
#define CP_COMMIT() asm volatile("cp.async.commit_group;" ::: "memory")
#define CP_WAIT0()  asm volatile("cp.async.wait_group 0;" ::: "memory")
#define CP_WAIT1()  asm volatile("cp.async.wait_group 1;" ::: "memory")

__device__ __forceinline__ void ldsm_x4(uint32_t* r, uint32_t addr) {
    asm volatile("ldmatrix.sync.aligned.m8n8.x4.shared.b16 {%0,%1,%2,%3}, [%4];"
                 : "=r"(r[0]), "=r"(r[1]), "=r"(r[2]), "=r"(r[3]) : "r"(addr));
}
__device__ __forceinline__ void mma_bf16(float* c, const uint32_t* a, const uint32_t* b) {
    asm volatile("mma.sync.aligned.m16n8k16.row.col.f32.bf16.bf16.f32 "
                 "{%0,%1,%2,%3}, {%4,%5,%6,%7}, {%8,%9}, {%0,%1,%2,%3};"
                 : "+f"(c[0]), "+f"(c[1]), "+f"(c[2]), "+f"(c[3])
                 : "r"(a[0]), "r"(a[1]), "r"(a[2]), "r"(a[3]), "r"(b[0]), "r"(b[1]));
}
__device__ __forceinline__ uint32_t swz(uint32_t off) {   // SW128-style XOR swizzle
    return off ^ ((off >> 3) & 0x70);
}

// ---------------------------------------------------------------------------
// HMMA split-bf16 GEMM, fused passes: per 64-wide k-chunk load Ahi,Alo,Bhi,Blo
// once, issue 3 products (Ahi.Bhi + Ahi.Blo + Alo.Bhi), fp32 accum.
// A:[M,K] row-major, B:[N,K] row-major (== col-major B operand for mma).
// BK=64. Warp computes WM x WN. THREADS = (BM/WM)*(BN/WN)*32.
// Dyn smem layout per buffer: [Ahi | Alo | Bhi | Blo], tile row = 128B swizzled.
// ---------------------------------------------------------------------------
template <int BM, int BN, int WM, int WN, bool ADD, bool BIAS, bool OUT_SPLIT>
__global__ __launch_bounds__((BM / WM) * (BN / WN) * 32) void rnn_gemm(
    int M, int N, int K,
    const __nv_bfloat16* __restrict__ Ahi, const __nv_bfloat16* __restrict__ Alo,
    const __nv_bfloat16* __restrict__ Bhi, const __nv_bfloat16* __restrict__ Blo,
    const float* __restrict__ Add, int ldadd,
    const float* __restrict__ bias,
    float* __restrict__ C,
    __nv_bfloat16* __restrict__ Chi, __nv_bfloat16* __restrict__ Clo)
{
    constexpr int THREADS = (BM / WM) * (BN / WN) * 32;
    constexpr int ATILE = BM * 128;      // bytes per A tile (64 bf16 per row)
    constexpr int BTILE = BN * 128;
    constexpr int BUF = 2 * ATILE + 2 * BTILE;
    constexpr int MI = WM / 16, NI = WN / 8, NJ = WN / 16;

    extern __shared__ __align__(1024) char smem[];
    const uint32_t sbase = smem_to_u32(smem);

    const int tid  = threadIdx.x;
    const int lane = tid & 31;
    const int wid  = tid >> 5;
    constexpr int WARPS_N = BN / WN;
    const int warp_n = wid % WARPS_N;
    const int warp_m = wid / WARPS_N;
    const int bn = blockIdx.x;
    const int bm = blockIdx.y;

    const int NIT = K >> 6;

    auto issueTiles = [&](int it, int buf) {
        const int kb = it << 6;
        const char* AgH = (const char*)(Ahi + (size_t)(bm * BM) * K + kb);
        const char* AgL = (const char*)(Alo + (size_t)(bm * BM) * K + kb);
        const char* BgH = (const char*)(Bhi + (size_t)(bn * BN) * K + kb);
        const char* BgL = (const char*)(Blo + (size_t)(bn * BN) * K + kb);
        const uint32_t s0 = sbase + buf * BUF;
        const size_t rs = (size_t)K * 2;
#pragma unroll
        for (int j = 0; j < BM * 8 / THREADS; j++) {
            int c = tid + j * THREADS;
            int r = c >> 3, col = (c & 7) << 4;
            uint32_t off = swz((uint32_t)(r * 128 + col));
            size_t g = (size_t)r * rs + col;
            CP_ASYNC16(s0 + off, AgH + g);
            CP_ASYNC16(s0 + ATILE + off, AgL + g);
        }
#pragma unroll
        for (int j = 0; j < BN * 8 / THREADS; j++) {
            int c = tid + j * THREADS;
            int r = c >> 3, col = (c & 7) << 4;
            uint32_t off = swz((uint32_t)(r * 128 + col));
            size_t g = (size_t)r * rs + col;
            CP_ASYNC16(s0 + 2 * ATILE + off, BgH + g);
            CP_ASYNC16(s0 + 2 * ATILE + BTILE + off, BgL + g);
        }
    };

    float acc[MI][NI][4];
#pragma unroll
    for (int i = 0; i < MI; i++)
#pragma unroll
        for (int j = 0; j < NI; j++)
#pragma unroll
            for (int e = 0; e < 4; e++) acc[i][j][e] = 0.0f;

    issueTiles(0, 0);
    CP_COMMIT();

    for (int it = 0; it < NIT; it++) {
        const int buf = it & 1;
        if (it + 1 < NIT) {
            issueTiles(it + 1, buf ^ 1);
            CP_COMMIT();
            CP_WAIT1();
        } else {
            CP_WAIT0();
        }
        __syncthreads();

        const uint32_t sAh = sbase + buf * BUF;
        const uint32_t sAl = sAh + ATILE;
        const uint32_t sBh = sAh + 2 * ATILE;
        const uint32_t sBl = sBh + BTILE;
#pragma unroll
        for (int s = 0; s < 4; s++) {    // 4 x k16 within BK=64
            const int k0 = s * 16;
            uint32_t ah[MI][4], al[MI][4], bh[NJ][4], bl[NJ][4];
#pragma unroll
            for (int i = 0; i < MI; i++) {
                int row = warp_m * WM + i * 16 + (lane & 15);
                int kc  = k0 + (lane >> 4) * 8;
                uint32_t off = swz((uint32_t)(row * 128 + kc * 2));
                ldsm_x4(ah[i], sAh + off);
                ldsm_x4(al[i], sAl + off);
            }
#pragma unroll
            for (int j = 0; j < NJ; j++) {
                int n  = warp_n * WN + j * 16 + (lane & 7) + ((lane >> 4) & 1) * 8;
                int kc = k0 + ((lane >> 3) & 1) * 8;
                uint32_t off = swz((uint32_t)(n * 128 + kc * 2));
                ldsm_x4(bh[j], sBh + off);
                ldsm_x4(bl[j], sBl + off);
            }
#pragma unroll
            for (int i = 0; i < MI; i++)
#pragma unroll
                for (int j = 0; j < NI; j++) {
                    mma_bf16(acc[i][j], ah[i], &bh[j >> 1][(j & 1) * 2]);
                    mma_bf16(acc[i][j], ah[i], &bl[j >> 1][(j & 1) * 2]);
                    mma_bf16(acc[i][j], al[i], &bh[j >> 1][(j & 1) * 2]);
                }
        }
        __syncthreads();
    }

    // ---- epilogue ----
    const int tg = lane >> 2, tr = lane & 3;
    const int m_base = bm * BM + warp_m * WM;
    const int n_base = bn * BN + warp_n * WN;
#pragma unroll
    for (int i = 0; i < MI; i++) {
#pragma unroll
        for (int j = 0; j < NI; j++) {
            const int col  = n_base + j * 8 + tr * 2;
            const int row0 = m_base + i * 16 + tg;
            const int row1 = row0 + 8;
            float2 v0 = make_float2(acc[i][j][0], acc[i][j][1]);
            float2 v1 = make_float2(acc[i][j][2], acc[i][j][3]);
            if (ADD) {
                float2 a0 = *(const float2*)&Add[(size_t)row0 * ldadd + col];
                float2 a1 = *(const float2*)&Add[(size_t)row1 * ldadd + col];
                v0.x += a0.x; v0.y += a0.y; v1.x += a1.x; v1.y += a1.y;
            }
            if (BIAS) {
                float2 bb = *(const float2*)&bias[col];
                v0.x += bb.x; v0.y += bb.y; v1.x += bb.x; v1.y += bb.y;
            }
            if (OUT_SPLIT) {
                __nv_bfloat16 h0 = __float2bfloat16(v0.x), h1 = __float2bfloat16(v0.y);
                __nv_bfloat16 h2 = __float2bfloat16(v1.x), h3 = __float2bfloat16(v1.y);
                __nv_bfloat16 l0 = __float2bfloat16(v0.x - __bfloat162float(h0));
                __nv_bfloat16 l1 = __float2bfloat16(v0.y - __bfloat162float(h1));
                __nv_bfloat16 l2 = __float2bfloat16(v1.x - __bfloat162float(h2));
                __nv_bfloat16 l3 = __float2bfloat16(v1.y - __bfloat162float(h3));
                __nv_bfloat162 hp0{h0, h1}, hp1{h2, h3}, lp0{l0, l1}, lp1{l2, l3};
                *(uint32_t*)&Chi[(size_t)row0 * N + col] = *(uint32_t*)&hp0;
                *(uint32_t*)&Chi[(size_t)row1 * N + col] = *(uint32_t*)&hp1;
                *(uint32_t*)&Clo[(size_t)row0 * N + col] = *(uint32_t*)&lp0;
                *(uint32_t*)&Clo[(size_t)row1 * N + col] = *(uint32_t*)&lp1;
            } else {
                *(float2*)&C[(size_t)row0 * N + col] = v0;
                *(float2*)&C[(size_t)row1 * N + col] = v1;
            }
        }
    }
}

// ---------------- fp32 -> bf16 hi/lo split kernels --------------------------
__global__ void split_kernel(const float* __restrict__ src,
                             __nv_bfloat16* __restrict__ hi, __nv_bfloat16* __restrict__ lo,
                             size_t n4)
{
    size_t i = (size_t)blockIdx.x * blockDim.x + threadIdx.x;
    if (i >= n4) return;
    float4 v = ((const float4*)src)[i];
    __nv_bfloat16 h0 = __float2bfloat16(v.x), h1 = __float2bfloat16(v.y);
    __nv_bfloat16 h2 = __float2bfloat16(v.z), h3 = __float2bfloat16(v.w);
    __nv_bfloat16 l0 = __float2bfloat16(v.x - __bfloat162float(h0));
    __nv_bfloat16 l1 = __float2bfloat16(v.y - __bfloat162float(h1));
    __nv_bfloat16 l2 = __float2bfloat16(v.z - __bfloat162float(h2));
    __nv_bfloat16 l3 = __float2bfloat16(v.w - __bfloat162float(h3));
    __nv_bfloat162 hp0{h0, h1}, hp1{h2, h3}, lp0{l0, l1}, lp1{l2, l3};
    uint2 hw, lw;
    hw.x = *(uint32_t*)&hp0; hw.y = *(uint32_t*)&hp1;
    lw.x = *(uint32_t*)&lp0; lw.y = *(uint32_t*)&lp1;
    ((uint2*)hi)[i] = hw;
    ((uint2*)lo)[i] = lw;
}

__global__ void split_h0_kernel(const float* __restrict__ xproj,
                                __nv_bfloat16* __restrict__ hi, __nv_bfloat16* __restrict__ lo)
{
    size_t i = (size_t)blockIdx.x * blockDim.x + threadIdx.x;
    size_t n4 = (size_t)BATCH * D_HID / 4;
    if (i >= n4) return;
    size_t e = i * 4;
    size_t b = e / D_HID, c = e % D_HID;
    float4 v = *(const float4*)&xproj[b * (size_t)SEQ * D_HID + c];
    __nv_bfloat16 h0 = __float2bfloat16(v.x), h1 = __float2bfloat16(v.y);
    __nv_bfloat16 h2 = __float2bfloat16(v.z), h3 = __float2bfloat16(v.w);
    __nv_bfloat16 l0 = __float2bfloat16(v.x - __bfloat162float(h0));
    __nv_bfloat16 l1 = __float2bfloat16(v.y - __bfloat162float(h1));
    __nv_bfloat16 l2 = __float2bfloat16(v.z - __bfloat162float(h2));
    __nv_bfloat16 l3 = __float2bfloat16(v.w - __bfloat162float(h3));
    __nv_bfloat162 hp0{h0, h1}, hp1{h2, h3}, lp0{l0, l1}, lp1{l2, l3};
    uint2 hw, lw;
    hw.x = *(uint32_t*)&hp0; hw.y = *(uint32_t*)&hp1;
    lw.x = *(uint32_t*)&lp0; lw.y = *(uint32_t*)&lp1;
    ((uint2*)hi)[i] = hw;
    ((uint2*)lo)[i] = lw;
}

// ---------------------------------------------------------------------------
extern "C" void kernel_launch(void* const* d_in, const int* in_sizes, int n_in,
                              void* d_out, int out_size)
{
    const float* x    = (const float*)d_in[0];
    const float* W_hx = (const float*)d_in[1];
    const float* W_hh = (const float*)d_in[2];
    const float* W_ph = (const float*)d_in[3];
    const float* b_h  = (const float*)d_in[4];
    const float* b_p  = (const float*)d_in[5];
    float* out = (float*)d_out;

    float* xproj; __nv_bfloat16 *x_hi, *x_lo, *whh_hi, *whh_lo, *whx_hi, *whx_lo,
                  *wph_hi, *wph_lo, *h_hi, *h_lo;
    cudaGetSymbolAddress((void**)&xproj,  g_xproj);
    cudaGetSymbolAddress((void**)&x_hi,   g_x_hi);
    cudaGetSymbolAddress((void**)&x_lo,   g_x_lo);
    cudaGetSymbolAddress((void**)&whh_hi, g_Whh_hi);
    cudaGetSymbolAddress((void**)&whh_lo, g_Whh_lo);
    cudaGetSymbolAddress((void**)&whx_hi, g_Whx_hi);
    cudaGetSymbolAddress((void**)&whx_lo, g_Whx_lo);
    cudaGetSymbolAddress((void**)&wph_hi, g_Wph_hi);
    cudaGetSymbolAddress((void**)&wph_lo, g_Wph_lo);
    cudaGetSymbolAddress((void**)&h_hi,   g_h_hi);
    cudaGetSymbolAddress((void**)&h_lo,   g_h_lo);

    // instantiations + their dyn smem sizes
    auto kXproj = rnn_gemm<128, 128, 64, 32, false, true, false>;
    auto kStep  = rnn_gemm<64, 64, 32, 32, true, false, true>;
    auto kOut   = rnn_gemm<64, 64, 32, 32, false, true, false>;
    const int SMEM_XPROJ = 2 * (2 * 128 * 128 + 2 * 128 * 128);  // 131072
    const int SMEM_64    = 2 * (2 * 64 * 128 + 2 * 64 * 128);    // 65536
    cudaFuncSetAttribute(kXproj, cudaFuncAttributeMaxDynamicSharedMemorySize, SMEM_XPROJ);
    cudaFuncSetAttribute(kStep,  cudaFuncAttributeMaxDynamicSharedMemorySize, SMEM_64);
    cudaFuncSetAttribute(kOut,   cudaFuncAttributeMaxDynamicSharedMemorySize, SMEM_64);

    // 0) splits of inputs/weights
    {
        size_t n4;
        n4 = (size_t)BATCH * SEQ * D_IN / 4;
        split_kernel<<<(unsigned)((n4 + 255) / 256), 256>>>(x, x_hi, x_lo, n4);
        n4 = (size_t)D_HID * D_HID / 4;
        split_kernel<<<(unsigned)((n4 + 255) / 256), 256>>>(W_hh, whh_hi, whh_lo, n4);
        n4 = (size_t)D_HID * D_IN / 4;
        split_kernel<<<(unsigned)((n4 + 255) / 256), 256>>>(W_hx, whx_hi, whx_lo, n4);
        n4 = (size_t)N_CLS * D_HID / 4;
        split_kernel<<<(unsigned)((n4 + 255) / 256), 256>>>(W_ph, wph_hi, wph_lo, n4);
    }

    // 1) xproj = x @ W_hx^T + b_h   (M=32768, N=2048, K=1024) -> fp32
    {
        dim3 grid(D_HID / 128, (BATCH * SEQ) / 128);
        kXproj<<<grid, 256, SMEM_XPROJ>>>(
            BATCH * SEQ, D_HID, D_IN,
            x_hi, x_lo, whx_hi, whx_lo,
            nullptr, 0, b_h, xproj, nullptr, nullptr);
    }

    // 2) h0 = xp_0 -> bf16 hi/lo
    {
        size_t n4 = (size_t)BATCH * D_HID / 4;
        split_h0_kernel<<<(unsigned)((n4 + 255) / 256), 256>>>(xproj, h_hi, h_lo);
    }

    // 3) recurrence: h_t = xp_t + h_{t-1} @ W_hh^T  (M=256, N=2048, K=2048)
    const size_t HB = (size_t)BATCH * D_HID;
    int cur = 0;
    for (int t = 1; t < SEQ; t++) {
        int nxt = t & 1;
        dim3 grid(D_HID / 64, BATCH / 64);
        kStep<<<grid, 128, SMEM_64>>>(
            BATCH, D_HID, D_HID,
            h_hi + (size_t)cur * HB, h_lo + (size_t)cur * HB,
            whh_hi, whh_lo,
            xproj + (size_t)t * D_HID, SEQ * D_HID,
            nullptr, nullptr,
            h_hi + (size_t)nxt * HB, h_lo + (size_t)nxt * HB);
        cur = nxt;
    }

    // 4) readout: out = h_T @ W_ph^T + b_p  (M=256, N=1024, K=2048) -> fp32
    {
        dim3 grid(N_CLS / 64, BATCH / 64);
        kOut<<<grid, 128, SMEM_64>>>(
            BATCH, N_CLS, D_HID,
            h_hi + (size_t)cur * HB, h_lo + (size_t)cur * HB,
            wph_hi, wph_lo,
            nullptr, 0, b_p, out, nullptr, nullptr);
    }
}